// round 5
// baseline (speedup 1.0000x reference)
#include <cuda_runtime.h>
#include <math.h>
#include <stdint.h>

// ---------------- problem constants ----------------
#define N_NODES 50000
#define N_REL   50
#define N_BASES 30
#define NSEG    (N_NODES * N_REL)
#define MAXE    1100000
#define SCAN_CHUNK 2048
#define NB2 ((NSEG + SCAN_CHUNK - 1) / SCAN_CHUNK)
#define FULLM 0xffffffffu

// ---------------- static device scratch ----------------
__device__ int d_cnt[NSEG];
__device__ int d_off[NSEG + 1];
__device__ int d_cpt[NSEG + 1];
__device__ int d_cur[NSEG];
__device__ int d_coff[MAXE + 2];
__device__ int d_cdst[MAXE];
__device__ int d_srcn[MAXE];
__device__ unsigned long long d_agg[NB2];
__device__ unsigned long long d_incl[NB2];
__device__ int d_stat[NB2];
__device__ int d_bidc;
__device__ float d_W[N_REL * 64 * 64];
__device__ float d_msg[N_NODES * 64];
__device__ float d_hA[N_NODES * 64];
__device__ float d_hB[N_NODES * 64];

__device__ __forceinline__ float tf32r(float v) {
    uint32_t u;
    asm("cvt.rna.tf32.f32 %0, %1;" : "=r"(u) : "f"(v));
    return __uint_as_float(u);
}
__device__ __forceinline__ void red4(float* p, float a, float b, float c, float d) {
    asm volatile("red.global.add.v4.f32 [%0], {%1, %2, %3, %4};"
                 :: "l"(p), "f"(a), "f"(b), "f"(c), "f"(d) : "memory");
}

// ---------------- setup kernels ----------------
__global__ void k_zero() {
    int i = blockIdx.x * blockDim.x + threadIdx.x;
    if (i < NSEG) d_cnt[i] = 0;
    if (i < N_NODES * 64) d_msg[i] = 0.f;
    if (i < NB2) d_stat[i] = 0;
    if (i == 0) d_bidc = 0;
}

__global__ void k_hist(const int* __restrict__ et, const int* __restrict__ dst, int E) {
    int e = blockIdx.x * blockDim.x + threadIdx.x;
    if (e < E) atomicAdd(&d_cnt[et[e] * N_NODES + dst[e]], 1);
}

// single-pass decoupled-lookback scan of (cnt, cnt>0)
__global__ void __launch_bounds__(256) k_scan() {
    __shared__ int sbid;
    __shared__ unsigned long long sexcl;
    __shared__ int ssum[256], sflg[256];
    int t = threadIdx.x;
    if (t == 0) sbid = atomicAdd(&d_bidc, 1);
    __syncthreads();
    int bid = sbid;
    int base = bid * SCAN_CHUNK + t * 8;
    int v[8], f[8];
    int run1 = 0, run2 = 0;
#pragma unroll
    for (int j = 0; j < 8; j++) {
        int idx = base + j;
        int c = (idx < NSEG) ? d_cnt[idx] : 0;
        v[j] = run1; f[j] = run2;
        run1 += c; run2 += (c > 0);
    }
    ssum[t] = run1; sflg[t] = run2;
    __syncthreads();
    for (int d = 1; d < 256; d <<= 1) {
        int a = 0, b = 0;
        if (t >= d) { a = ssum[t - d]; b = sflg[t - d]; }
        __syncthreads();
        if (t >= d) { ssum[t] += a; sflg[t] += b; }
        __syncthreads();
    }
    unsigned long long blockAgg =
        ((unsigned long long)(unsigned)ssum[255] << 32) | (unsigned)sflg[255];
    if (t == 0) {
        *((volatile unsigned long long*)&d_agg[bid]) = blockAgg;
        __threadfence();
        *((volatile int*)&d_stat[bid]) = 1;
    }
    if (t < 32) {
        unsigned long long excl = 0;
        int p = bid - 1;
        while (p >= 0) {
            int pi = p - t;
            int st;
            do {
                st = (pi >= 0) ? *((volatile int*)&d_stat[pi]) : 2;
            } while (__any_sync(FULLM, st == 0));
            unsigned m2 = __ballot_sync(FULLM, pi >= 0 && st == 2);
            if (m2) {
                int lead = __ffs(m2) - 1;
                unsigned long long vv = 0ull;
                if (pi >= 0) {
                    if (t < lead)       vv = *((volatile unsigned long long*)&d_agg[pi]);
                    else if (t == lead) vv = *((volatile unsigned long long*)&d_incl[pi]);
                }
                for (int o = 16; o > 0; o >>= 1) vv += __shfl_down_sync(FULLM, vv, o);
                excl += __shfl_sync(FULLM, vv, 0);
                break;
            } else {
                unsigned long long vv =
                    (pi >= 0) ? *((volatile unsigned long long*)&d_agg[pi]) : 0ull;
                for (int o = 16; o > 0; o >>= 1) vv += __shfl_down_sync(FULLM, vv, o);
                excl += __shfl_sync(FULLM, vv, 0);
                p -= 32;
            }
        }
        if (t == 0) {
            sexcl = excl;
            *((volatile unsigned long long*)&d_incl[bid]) = excl + blockAgg;
            __threadfence();
            *((volatile int*)&d_stat[bid]) = 2;
        }
    }
    __syncthreads();
    int exS = (int)(sexcl >> 32), exF = (int)(sexcl & 0xffffffffu);
    int ts = exS + ssum[t] - run1;
    int tf = exF + sflg[t] - run2;
#pragma unroll
    for (int j = 0; j < 8; j++) {
        int idx = base + j;
        if (idx < NSEG) {
            int o = ts + v[j];
            d_off[idx] = o; d_cur[idx] = o; d_cpt[idx] = tf + f[j];
        }
    }
    if (bid == NB2 - 1 && t == 255) {
        d_off[NSEG] = exS + ssum[255];
        d_cpt[NSEG] = exF + sflg[255];
    }
}

__global__ void k_cscat(const int* __restrict__ et, const int* __restrict__ dst,
                        const int* __restrict__ src, int E) {
    int i = blockIdx.x * blockDim.x + threadIdx.x;
    if (i < NSEG && d_cnt[i] > 0) {
        int c = d_cpt[i];
        d_coff[c] = d_off[i];
        d_cdst[c] = i % N_NODES;
    }
    if (i < E) {
        int key = et[i] * N_NODES + dst[i];
        int p = atomicAdd(&d_cur[key], 1);
        d_srcn[p] = src[i];
    }
    if (i == 0) d_coff[d_cpt[NSEG]] = E;
}

// ---------------- per-layer kernels ----------------
__global__ void k_W(const float* __restrict__ bases, const float* __restrict__ comp, int dout) {
    int idx = blockIdx.x * blockDim.x + threadIdx.x;
    int tot = N_REL * 64 * dout;
    if (idx >= tot) return;
    int r = idx / (64 * dout);
    int ko = idx - r * 64 * dout;
    float acc = 0.f;
#pragma unroll 6
    for (int b = 0; b < N_BASES; b++)
        acc += comp[r * N_BASES + b] * bases[b * 64 * dout + ko];
    d_W[idx] = tf32r(acc);
}

// Fused mean aggregation (batched MLP-16 streaming) + tf32 MMA + red4 scatter.
template <int DOUT>
__global__ void __launch_bounds__(256) k_agg(const float* __restrict__ x) {
    constexpr int WS = (DOUT == 64) ? 68 : 8;
    extern __shared__ float smem[];
    float* Ws = smem;               // [64][WS]
    float* As = smem + 64 * WS;     // [128][68] warp-private 16-row stripes

    int r = blockIdx.y;
    int t = threadIdx.x, lane = t & 31, w = t >> 5;

    int baseC = d_cpt[r * N_NODES];
    int Cend  = d_cpt[(r + 1) * N_NODES];
    int row0  = blockIdx.x * 128;
    if (baseC + row0 >= Cend) return;

    const float* Wr = d_W + r * 64 * DOUT;
    if (DOUT == 64) {
        for (int i = t; i < 64 * 64; i += 256)
            Ws[(i >> 6) * 68 + (i & 63)] = Wr[i];
    } else {
        for (int i = t; i < 64 * 8; i += 256) Ws[i] = Wr[i];
    }

    int cbase = baseC + row0 + w * 16;
    // per-row metadata in registers (shfl-broadcast)
    int soV = d_coff[min(cbase + min(lane, 16), Cend)];
    int ciL = cbase + lane;
    int sdstV = (lane < 16 && ciL < Cend) ? d_cdst[ciL] : -1;

    float* myA = As + (w * 16) * 68;

    // ---- pass 1: first edge of every row (16 independent loads) ----
    int sn[16];
#pragma unroll
    for (int rr = 0; rr < 16; rr++) {
        int e0 = __shfl_sync(FULLM, soV, rr);
        int e1 = __shfl_sync(FULLM, soV, rr + 1);
        sn[rr] = (e1 > e0) ? __ldg(&d_srcn[e0]) : -1;
    }
    float2 acc[16];
#pragma unroll
    for (int rr = 0; rr < 16; rr++) {
        acc[rr] = (sn[rr] >= 0) ? *(const float2*)(x + sn[rr] * 64 + 2 * lane)
                                : make_float2(0.f, 0.f);
    }
    // ---- pass 2: second edge where count >= 2 ----
#pragma unroll
    for (int rr = 0; rr < 16; rr++) {
        int e0 = __shfl_sync(FULLM, soV, rr);
        int e1 = __shfl_sync(FULLM, soV, rr + 1);
        sn[rr] = (e1 - e0 >= 2) ? __ldg(&d_srcn[e0 + 1]) : -1;
    }
#pragma unroll
    for (int rr = 0; rr < 16; rr++) {
        if (sn[rr] >= 0) {
            float2 xv = *(const float2*)(x + sn[rr] * 64 + 2 * lane);
            acc[rr].x += xv.x; acc[rr].y += xv.y;
        }
    }
    // ---- pass 3: rare rows with count >= 3 (uniform branches, no divergence) ----
#pragma unroll
    for (int rr = 0; rr < 16; rr++) {
        int e0 = __shfl_sync(FULLM, soV, rr);
        int e1 = __shfl_sync(FULLM, soV, rr + 1);
        for (int e = e0 + 2; e < e1; e++) {
            int s = __ldg(&d_srcn[e]);
            float2 xv = *(const float2*)(x + s * 64 + 2 * lane);
            acc[rr].x += xv.x; acc[rr].y += xv.y;
        }
        float inv = (e1 > e0) ? 1.f / (float)(e1 - e0) : 0.f;
        myA[rr * 68 + 2 * lane]     = tf32r(acc[rr].x * inv);
        myA[rr * 68 + 2 * lane + 1] = tf32r(acc[rr].y * inv);
    }
    __syncthreads();   // Ws visible to all; As stripes warp-private

    if (DOUT == 64) {
        int g = lane >> 2, q = lane & 3;
        const float* Ar0 = As + (w * 16 + g) * 68;
        const float* Ar8 = Ar0 + 8 * 68;
        float mac[8][4];
#pragma unroll
        for (int j = 0; j < 8; j++)
#pragma unroll
            for (int i = 0; i < 4; i++) mac[j][i] = 0.f;
#pragma unroll
        for (int kk = 0; kk < 8; kk++) {
            int k0 = kk * 8;
            uint32_t A0 = __float_as_uint(Ar0[k0 + q]);
            uint32_t A1 = __float_as_uint(Ar8[k0 + q]);
            uint32_t A2 = __float_as_uint(Ar0[k0 + q + 4]);
            uint32_t A3 = __float_as_uint(Ar8[k0 + q + 4]);
#pragma unroll
            for (int j = 0; j < 8; j++) {
                uint32_t B0 = __float_as_uint(Ws[(k0 + q) * 68 + j * 8 + g]);
                uint32_t B1 = __float_as_uint(Ws[(k0 + q + 4) * 68 + j * 8 + g]);
                asm volatile(
                    "mma.sync.aligned.m16n8k8.row.col.f32.tf32.tf32.f32 "
                    "{%0,%1,%2,%3}, {%4,%5,%6,%7}, {%8,%9}, {%0,%1,%2,%3};"
                    : "+f"(mac[j][0]), "+f"(mac[j][1]), "+f"(mac[j][2]), "+f"(mac[j][3])
                    : "r"(A0), "r"(A1), "r"(A2), "r"(A3), "r"(B0), "r"(B1));
            }
        }
        // transpose through warp-private smem stripe, then vector atomics
        __syncwarp();
#pragma unroll
        for (int j = 0; j < 8; j++) {
            int colb = j * 8 + 2 * q;
            myA[g * 68 + colb]           = mac[j][0];
            myA[g * 68 + colb + 1]       = mac[j][1];
            myA[(g + 8) * 68 + colb]     = mac[j][2];
            myA[(g + 8) * 68 + colb + 1] = mac[j][3];
        }
        __syncwarp();
        int row = lane >> 1;
        int c0 = (lane & 1) * 32;
        int dn = __shfl_sync(FULLM, sdstV, row);
        if (dn >= 0) {
            const float* Ar = myA + row * 68 + c0;
            float* outp = &d_msg[dn * 64 + c0];
#pragma unroll
            for (int k = 0; k < 8; k++) {
                float4 vv = *(const float4*)(Ar + k * 4);
                red4(outp + k * 4, vv.x, vv.y, vv.z, vv.w);
            }
        }
    } else {
        int row = lane >> 1;
        int c0 = (lane & 1) * 4;
        const float* Ar = As + (w * 16 + row) * 68;
        float s0 = 0.f, s1 = 0.f, s2 = 0.f, s3 = 0.f;
#pragma unroll
        for (int k = 0; k < 64; k++) {
            float a = Ar[k];
            float4 b = *(const float4*)&Ws[k * 8 + c0];
            s0 += a * b.x; s1 += a * b.y; s2 += a * b.z; s3 += a * b.w;
        }
        int dn = __shfl_sync(FULLM, sdstV, row);
        if (dn >= 0) red4(&d_msg[dn * 8 + c0], s0, s1, s2, s3);
    }
}

// epilogue: h = relu(msg + x@root + bias); re-zero msg
__global__ void k_rootrelu(const float* __restrict__ x, const float* __restrict__ root,
                           const float* __restrict__ bias, float* __restrict__ h) {
    int idx = blockIdx.x * blockDim.x + threadIdx.x;
    if (idx >= N_NODES * 64) return;
    int n = idx >> 6, o = idx & 63;
    float acc = bias[o] + d_msg[idx];
    d_msg[idx] = 0.f;
    const float* xr = x + n * 64;
#pragma unroll 16
    for (int i = 0; i < 64; i++) acc += xr[i] * root[i * 64 + o];
    h[idx] = acc > 0.f ? acc : 0.f;
}

__global__ void k_rootlsm(const float* __restrict__ x, const float* __restrict__ root,
                          const float* __restrict__ bias, float* __restrict__ out) {
    int n = blockIdx.x * blockDim.x + threadIdx.x;
    if (n >= N_NODES) return;
    float v[8];
#pragma unroll
    for (int c = 0; c < 8; c++) v[c] = bias[c] + d_msg[n * 8 + c];
    const float* xr = x + n * 64;
    for (int i = 0; i < 64; i++) {
        float xv = xr[i];
#pragma unroll
        for (int c = 0; c < 8; c++) v[c] += xv * root[i * 8 + c];
    }
    float m = -1e30f;
#pragma unroll
    for (int c = 0; c < 8; c++) m = fmaxf(m, v[c]);
    float s = 0.f;
#pragma unroll
    for (int c = 0; c < 8; c++) s += expf(v[c] - m);
    float ls = logf(s) + m;
#pragma unroll
    for (int c = 0; c < 8; c++) out[n * 8 + c] = v[c] - ls;
}

// ---------------- launch ----------------
extern "C" void kernel_launch(void* const* d_in, const int* in_sizes, int n_in,
                              void* d_out, int out_size) {
    const float* x0 = (const float*)d_in[0];
    const int* ei = (const int*)d_in[1];
    const int* et = (const int*)d_in[2];
    int E = in_sizes[2];
    const int* src = ei;
    const int* dst = ei + E;

    void *pA, *pB;
    cudaGetSymbolAddress(&pA, d_hA);
    cudaGetSymbolAddress(&pB, d_hB);
    float* hA = (float*)pA;
    float* hB = (float*)pB;

    const int SMEM64 = (64 * 68 + 128 * 68) * 4;
    const int SMEM8  = (64 * 8  + 128 * 68) * 4;
    cudaFuncSetAttribute(k_agg<64>, cudaFuncAttributeMaxDynamicSharedMemorySize, SMEM64);
    cudaFuncSetAttribute(k_agg<8>,  cudaFuncAttributeMaxDynamicSharedMemorySize, SMEM8);

    const int NZ = N_NODES * 64;
    k_zero<<<(NZ + 255) / 256, 256>>>();
    k_hist<<<(E + 255) / 256, 256>>>(et, dst, E);
    k_scan<<<NB2, 256>>>();
    k_cscat<<<(NSEG + 255) / 256, 256>>>(et, dst, src, E);

    dim3 grid((N_NODES + 127) / 128, N_REL);

    k_W<<<(N_REL * 64 * 64 + 255) / 256, 256>>>((const float*)d_in[3], (const float*)d_in[4], 64);
    k_agg<64><<<grid, 256, SMEM64>>>(x0);
    k_rootrelu<<<(NZ + 255) / 256, 256>>>(x0, (const float*)d_in[5], (const float*)d_in[6], hA);

    k_W<<<(N_REL * 64 * 64 + 255) / 256, 256>>>((const float*)d_in[7], (const float*)d_in[8], 64);
    k_agg<64><<<grid, 256, SMEM64>>>(hA);
    k_rootrelu<<<(NZ + 255) / 256, 256>>>(hA, (const float*)d_in[9], (const float*)d_in[10], hB);

    k_W<<<(N_REL * 64 * 8 + 255) / 256, 256>>>((const float*)d_in[11], (const float*)d_in[12], 8);
    k_agg<8><<<grid, 256, SMEM8>>>(hB);
    k_rootlsm<<<(N_NODES + 255) / 256, 256>>>(hB, (const float*)d_in[13], (const float*)d_in[14],
                                              (float*)d_out);
}